// round 2
// baseline (speedup 1.0000x reference)
#include <cuda_runtime.h>
#include <math.h>

// Problem constants
#define BB 4
#define NN 4096
#define DD 512

// Scratch (device globals: allocation-free rule)
__device__ float g_E[(size_t)BB * NN * NN];   // 268 MB: scaled masked-exp matrix
__device__ float g_y[(size_t)BB * NN * DD];   // 32 MB : y = x @ w
__device__ float g_s[BB * NN];                // per-row score s = y @ a

// ---------------------------------------------------------------------------
// SGEMM: C[M,N] = A[M,K] @ B[K,N], fp32, 128x128 block tile, BK=8,
// 256 threads, 8x8 register tile per thread. blockIdx.z = batch.
// All dims are multiples of tile sizes for this problem (no bounds checks).
// ---------------------------------------------------------------------------
__global__ void __launch_bounds__(256, 2) sgemm128(
    const float* __restrict__ Ag, const float* __restrict__ Bg,
    float* __restrict__ Cg, int M, int N, int K,
    size_t sA, size_t sB, size_t sC)
{
    const float* A = Ag + (size_t)blockIdx.z * sA;
    const float* B = Bg + (size_t)blockIdx.z * sB;
    float*       C = Cg + (size_t)blockIdx.z * sC;

    __shared__ float As[8][128];   // transposed A tile: As[k][m]
    __shared__ float Bs[8][128];   // Bs[k][n]

    const int tid  = threadIdx.x;
    const int brow = blockIdx.y * 128;
    const int bcol = blockIdx.x * 128;
    const int tx = tid & 15;       // 16 threads across N
    const int ty = tid >> 4;       // 16 threads across M

    // Global-load mapping: A tile is 128x8 (one float4 per thread),
    // B tile is 8x128 (one float4 per thread).
    const int aRow = tid >> 1;
    const int aCol = (tid & 1) * 4;
    const int bRow = tid >> 5;
    const int bCol = (tid & 31) * 4;

    float acc[8][8];
#pragma unroll
    for (int i = 0; i < 8; i++)
#pragma unroll
        for (int j = 0; j < 8; j++) acc[i][j] = 0.f;

    const float* Aptr = A + (size_t)(brow + aRow) * K + aCol;
    const float* Bptr = B + (size_t)bRow * N + bcol + bCol;

    for (int k0 = 0; k0 < K; k0 += 8) {
        float4 av = *(const float4*)(Aptr + k0);
        As[aCol + 0][aRow] = av.x;
        As[aCol + 1][aRow] = av.y;
        As[aCol + 2][aRow] = av.z;
        As[aCol + 3][aRow] = av.w;
        float4 bv = *(const float4*)(Bptr + (size_t)k0 * N);
        *(float4*)(&Bs[bRow][bCol]) = bv;
        __syncthreads();

#pragma unroll
        for (int k = 0; k < 8; k++) {
            float ra[8], rb[8];
            // float4 LDS (aligned: rows are 128 floats)
            *(float4*)(ra)     = *(const float4*)(&As[k][ty * 8]);
            *(float4*)(ra + 4) = *(const float4*)(&As[k][ty * 8 + 4]);
            *(float4*)(rb)     = *(const float4*)(&Bs[k][tx * 8]);
            *(float4*)(rb + 4) = *(const float4*)(&Bs[k][tx * 8 + 4]);
#pragma unroll
            for (int i = 0; i < 8; i++)
#pragma unroll
                for (int j = 0; j < 8; j++)
                    acc[i][j] = fmaf(ra[i], rb[j], acc[i][j]);
        }
        __syncthreads();
    }

#pragma unroll
    for (int i = 0; i < 8; i++) {
        float* Crow = C + (size_t)(brow + ty * 8 + i) * N + bcol + tx * 8;
        *(float4*)(Crow)     = make_float4(acc[i][0], acc[i][1], acc[i][2], acc[i][3]);
        *(float4*)(Crow + 4) = make_float4(acc[i][4], acc[i][5], acc[i][6], acc[i][7]);
    }
}

// ---------------------------------------------------------------------------
// s[row] = dot(y[row, :], a)   (row = b*N + i)
// ---------------------------------------------------------------------------
__global__ void __launch_bounds__(128) s_kernel(const float* __restrict__ a)
{
    const int row = blockIdx.x;
    const float* y = g_y + (size_t)row * DD;
    float sum = 0.f;
    for (int t = threadIdx.x; t < DD; t += 128) sum += y[t] * a[t];
#pragma unroll
    for (int o = 16; o; o >>= 1) sum += __shfl_xor_sync(0xffffffffu, sum, o);
    __shared__ float red[4];
    if ((threadIdx.x & 31) == 0) red[threadIdx.x >> 5] = sum;
    __syncthreads();
    if (threadIdx.x == 0) g_s[row] = red[0] + red[1] + red[2] + red[3];
}

// ---------------------------------------------------------------------------
// Per row (b,i): read A_shape row once, compute
//   E_ij = exp(leaky(8*tanh((s_i+s_j)/8))) * A_shape_ij
//   R_i  = sum_j E_ij ; deg_i = sum_j A_shape_ij ; scale = deg/R
// and write E_scaled row to g_E.  One block (256 thr) per row; row buffered
// in 16KB smem so A_shape is touched exactly once.
// ---------------------------------------------------------------------------
__global__ void __launch_bounds__(256) row_kernel(const float* __restrict__ A_shape)
{
    const int row = blockIdx.x;             // b*NN + i
    const int b   = row >> 12;              // /4096
    const float* arow = A_shape + (size_t)row * NN;
    const float* srow = g_s + (size_t)b * NN;
    const float  si   = g_s[row];

    __shared__ float Erow[NN];              // 16 KB
    float deg = 0.f, R = 0.f;

    for (int j = threadIdx.x; j < NN; j += 256) {
        float aj = arow[j];
        float z  = si + srow[j];
        float u  = z * 0.125f;
        // numerically stable tanh (z can be +-3000)
        float eu = __expf(-2.f * fabsf(u));
        float t  = (1.f - eu) / (1.f + eu);
        t = copysignf(t, u);
        float Av = 8.f * t;                 // in (-8, 8)
        Av = (Av >= 0.f) ? Av : 0.1f * Av;  // LeakyReLU(0.1)
        float e = __expf(Av) * aj;
        deg += aj;
        R   += e;
        Erow[j] = e;
    }

#pragma unroll
    for (int o = 16; o; o >>= 1) {
        deg += __shfl_xor_sync(0xffffffffu, deg, o);
        R   += __shfl_xor_sync(0xffffffffu, R, o);
    }
    __shared__ float wdeg[8], wR[8];
    __shared__ float s_scale;
    const int warp = threadIdx.x >> 5;
    if ((threadIdx.x & 31) == 0) { wdeg[warp] = deg; wR[warp] = R; }
    __syncthreads();
    if (threadIdx.x == 0) {
        float D = 0.f, Rt = 0.f;
#pragma unroll
        for (int w = 0; w < 8; w++) { D += wdeg[w]; Rt += wR[w]; }
        s_scale = D / Rt;
    }
    __syncthreads();
    const float sc = s_scale;

    float* eout = g_E + (size_t)row * NN;
    for (int j = threadIdx.x; j < NN; j += 256) eout[j] = Erow[j] * sc;
}

// ---------------------------------------------------------------------------
// kernel_launch
// inputs (metadata order): x [B,N,512], A_shape [B,N,N], w [512,512], a [512]
// output: out [B,N,512] float32
// ---------------------------------------------------------------------------
extern "C" void kernel_launch(void* const* d_in, const int* in_sizes, int n_in,
                              void* d_out, int out_size)
{
    const float* x       = (const float*)d_in[0];
    const float* A_shape = (const float*)d_in[1];
    const float* w       = (const float*)d_in[2];
    const float* a       = (const float*)d_in[3];
    float* out = (float*)d_out;

    float *pE, *pY;
    cudaGetSymbolAddress((void**)&pE, g_E);
    cudaGetSymbolAddress((void**)&pY, g_y);

    // 1) y = x @ w   (M=B*N=16384, N=512, K=512)
    {
        dim3 grid(DD / 128, (BB * NN) / 128, 1);
        sgemm128<<<grid, 256>>>(x, w, pY, BB * NN, DD, DD, 0, 0, 0);
    }
    // 2) s = y @ a
    s_kernel<<<BB * NN, 128>>>(a);
    // 3) build scaled E
    row_kernel<<<BB * NN, 256>>>(A_shape);
    // 4) out[b] = E[b] @ y[b]   (M=N=4096 rows, N=512, K=4096, per batch)
    {
        dim3 grid(DD / 128, NN / 128, BB);
        sgemm128<<<grid, 256>>>(pE, pY, out,
                                NN, DD, NN,
                                (size_t)NN * NN, (size_t)NN * DD, (size_t)NN * DD);
    }
}

// round 4
// speedup vs baseline: 2.1494x; 2.1494x over previous
#include <cuda_runtime.h>
#include <cuda_bf16.h>
#include <cstdint>
#include <math.h>

#define BB 4
#define NN 4096
#define DD 512

// ---------------- device scratch (allocation-free rule) ----------------
__device__ __nv_bfloat16 g_Eh[(size_t)BB * NN * NN];   // 134 MB
__device__ __nv_bfloat16 g_El[(size_t)BB * NN * NN];   // 134 MB
__device__ __nv_bfloat16 g_xh[(size_t)BB * NN * DD];
__device__ __nv_bfloat16 g_xl[(size_t)BB * NN * DD];
__device__ __nv_bfloat16 g_wth[DD * DD];
__device__ __nv_bfloat16 g_wtl[DD * DD];
__device__ float         g_y [(size_t)BB * NN * DD];   // fp32 y = x@w
__device__ __nv_bfloat16 g_yth[(size_t)BB * DD * NN];  // y^T split (B-operand layout)
__device__ __nv_bfloat16 g_ytl[(size_t)BB * DD * NN];
__device__ float         g_s [BB * NN];
__device__ float         g_v [DD];                     // v = w @ a

// ---------------- PTX helpers ----------------
__device__ __forceinline__ uint32_t smem_u32(const void* p) {
    uint32_t a;
    asm("{ .reg .u64 t; cvta.to.shared.u64 t, %1; cvt.u32.u64 %0, t; }" : "=r"(a) : "l"(p));
    return a;
}
__device__ __forceinline__ void cp16(uint32_t smem_addr, const void* gptr) {
    asm volatile("cp.async.cg.shared.global [%0], [%1], 16;" :: "r"(smem_addr), "l"(gptr));
}
#define CP_COMMIT() asm volatile("cp.async.commit_group;" ::: "memory")
template <int N> __device__ __forceinline__ void cp_wait() {
    asm volatile("cp.async.wait_group %0;" :: "n"(N) : "memory");
}
__device__ __forceinline__ void ldsm4(uint32_t& r0, uint32_t& r1, uint32_t& r2, uint32_t& r3,
                                      uint32_t addr) {
    asm volatile("ldmatrix.sync.aligned.m8n8.x4.shared.b16 {%0,%1,%2,%3}, [%4];"
                 : "=r"(r0), "=r"(r1), "=r"(r2), "=r"(r3) : "r"(addr));
}
__device__ __forceinline__ void mma16816(float* c, const uint32_t* a, const uint32_t* b) {
    asm volatile(
        "mma.sync.aligned.m16n8k16.row.col.f32.bf16.bf16.f32 "
        "{%0,%1,%2,%3}, {%4,%5,%6,%7}, {%8,%9}, {%0,%1,%2,%3};"
        : "+f"(c[0]), "+f"(c[1]), "+f"(c[2]), "+f"(c[3])
        : "r"(a[0]), "r"(a[1]), "r"(a[2]), "r"(a[3]), "r"(b[0]), "r"(b[1]));
}

// ---------------- split-bf16 mma.sync GEMM ----------------
// C[M,N] fp32 = (Ah+Al)[M,K] @ (Bh+Bl)[N,K]^T, 3 bf16 MMAs per tile-pair.
// CTA tile 128x128, BK=32, 3-stage cp.async pipeline, 8 warps (warp tile 32x64).
// smem rows padded to 80B -> conflict-free ldmatrix without swizzle.
#define ROWB 80
#define ABYTES (128 * ROWB)            // 10240 per matrix tile
#define STG_A_H 0
#define STG_A_L (ABYTES)
#define STG_B_H (2 * ABYTES)
#define STG_B_L (3 * ABYTES)
#define STAGE_BYTES (4 * ABYTES)       // 40960
#define STAGES 3
#define GEMM_SMEM (STAGES * STAGE_BYTES)   // 122880

__global__ void __launch_bounds__(256) gemm_mma(
    const __nv_bfloat16* __restrict__ Ah_, const __nv_bfloat16* __restrict__ Al_,
    const __nv_bfloat16* __restrict__ Bh_, const __nv_bfloat16* __restrict__ Bl_,
    float* __restrict__ C_,
    int K, int lda, int ldb, int ldc,
    long long sAz, long long sBz, long long sCz)
{
    extern __shared__ char smem[];
    const uint32_t sb = smem_u32(smem);
    const int tid  = threadIdx.x;
    const int wid  = tid >> 5;
    const int lane = tid & 31;
    const int bcol = blockIdx.x * 128;
    const int brow = blockIdx.y * 128;
    const __nv_bfloat16* Ah = Ah_ + (size_t)blockIdx.z * sAz;
    const __nv_bfloat16* Al = Al_ + (size_t)blockIdx.z * sAz;
    const __nv_bfloat16* Bh = Bh_ + (size_t)blockIdx.z * sBz;
    const __nv_bfloat16* Bl = Bl_ + (size_t)blockIdx.z * sBz;
    float* C = C_ + (size_t)blockIdx.z * sCz;

    const int warp_m = wid & 3;        // 4 warps down M
    const int warp_n = wid >> 2;       // 2 warps across N
    const int m_base = warp_m * 32;
    const int n_base = warp_n * 64;

    float acc[2][8][4];
#pragma unroll
    for (int t = 0; t < 2; t++)
#pragma unroll
        for (int n = 0; n < 8; n++)
#pragma unroll
            for (int j = 0; j < 4; j++) acc[t][n][j] = 0.f;

    const int NCH = K >> 5;            // K chunks of 32

    auto load_chunk = [&](int c, int s) {
        const int k0 = c << 5;
        const uint32_t base = sb + s * STAGE_BYTES;
#pragma unroll
        for (int i = 0; i < 2; i++) {
            int id = tid + (i << 8);              // 0..511
            int r  = id >> 2;                     // row 0..127
            int ch = id & 3;                      // 16B chunk 0..3
            uint32_t so = r * ROWB + ch * 16;
            size_t ga = (size_t)(brow + r) * lda + k0 + ch * 8;
            size_t gb = (size_t)(bcol + r) * ldb + k0 + ch * 8;
            cp16(base + STG_A_H + so, Ah + ga);
            cp16(base + STG_A_L + so, Al + ga);
            cp16(base + STG_B_H + so, Bh + gb);
            cp16(base + STG_B_L + so, Bl + gb);
        }
    };

    // ldmatrix lane-address offsets (within a stage, relative to matrix base)
    const uint32_t aoff = (uint32_t)(m_base + (lane & 15)) * ROWB + (lane >> 4) * 16;
    const uint32_t boff = (uint32_t)(n_base + (lane & 7) + ((lane >> 4) << 3)) * ROWB
                        + ((lane >> 3) & 1) * 16;

    auto compute = [&](int s) {
        const uint32_t base = sb + s * STAGE_BYTES;
#pragma unroll
        for (int kk = 0; kk < 2; kk++) {          // two k16 steps per chunk
            const uint32_t kb = kk * 32;          // 16 bf16 = 32 bytes
            uint32_t ah[2][4], al[2][4], bh[4][4], bl[4][4];
#pragma unroll
            for (int t = 0; t < 2; t++) {
                uint32_t a_ad = base + aoff + (uint32_t)t * (16 * ROWB) + kb;
                ldsm4(ah[t][0], ah[t][1], ah[t][2], ah[t][3], STG_A_H + a_ad);
                ldsm4(al[t][0], al[t][1], al[t][2], al[t][3], STG_A_L + a_ad);
            }
#pragma unroll
            for (int p = 0; p < 4; p++) {         // each covers n-tiles 2p, 2p+1
                uint32_t b_ad = base + boff + (uint32_t)p * (16 * ROWB) + kb;
                ldsm4(bh[p][0], bh[p][1], bh[p][2], bh[p][3], STG_B_H + b_ad);
                ldsm4(bl[p][0], bl[p][1], bl[p][2], bl[p][3], STG_B_L + b_ad);
            }
#pragma unroll
            for (int t = 0; t < 2; t++)
#pragma unroll
                for (int n = 0; n < 8; n++) {
                    const int p = n >> 1;
                    const uint32_t* fh = &bh[p][(n & 1) * 2];
                    const uint32_t* fl = &bl[p][(n & 1) * 2];
                    mma16816(acc[t][n], ah[t], fh);
                    mma16816(acc[t][n], ah[t], fl);
                    mma16816(acc[t][n], al[t], fh);
                }
        }
    };

    // prologue: prefetch 2 stages
    load_chunk(0, 0); CP_COMMIT();
    if (NCH > 1) load_chunk(1, 1);
    CP_COMMIT();

    for (int c = 0; c < NCH; c++) {
        cp_wait<1>();                  // stage c data resident (this thread)
        __syncthreads();               // all threads' data visible; buf (c+2)%3 free
        if (c + 2 < NCH) load_chunk(c + 2, (c + 2) % STAGES);
        CP_COMMIT();                   // uniform group counting (may be empty)
        compute(c % STAGES);
    }

    // epilogue: write fp32 accumulators
#pragma unroll
    for (int t = 0; t < 2; t++) {
        const int m0 = brow + m_base + t * 16 + (lane >> 2);
#pragma unroll
        for (int n = 0; n < 8; n++) {
            const int cn = bcol + n_base + n * 8 + (lane & 3) * 2;
            float2 v0 = make_float2(acc[t][n][0], acc[t][n][1]);
            float2 v1 = make_float2(acc[t][n][2], acc[t][n][3]);
            *(float2*)(C + (size_t)m0 * ldc + cn)       = v0;
            *(float2*)(C + (size_t)(m0 + 8) * ldc + cn) = v1;
        }
    }
}

// ---------------- small kernels ----------------
__global__ void __launch_bounds__(256) split_x_k(const float* __restrict__ x, int n) {
    int i = blockIdx.x * 256 + threadIdx.x;
    if (i < n) {
        float v = x[i];
        __nv_bfloat16 h = __float2bfloat16(v);
        g_xh[i] = h;
        g_xl[i] = __float2bfloat16(v - __bfloat162float(h));
    }
}

__global__ void __launch_bounds__(256) wt_split_k(const float* __restrict__ w) {
    int id = blockIdx.x * 256 + threadIdx.x;   // id = n*512 + k
    int n = id >> 9, k = id & 511;
    float v = w[k * DD + n];                   // wt[n][k] = w[k][n]
    __nv_bfloat16 h = __float2bfloat16(v);
    g_wth[id] = h;
    g_wtl[id] = __float2bfloat16(v - __bfloat162float(h));
}

__global__ void __launch_bounds__(128) v_k(const float* __restrict__ w, const float* __restrict__ a) {
    int k = blockIdx.x;
    float sum = 0.f;
    for (int t = threadIdx.x; t < DD; t += 128) sum += w[k * DD + t] * a[t];
#pragma unroll
    for (int o = 16; o; o >>= 1) sum += __shfl_xor_sync(0xffffffffu, sum, o);
    __shared__ float red[4];
    if ((threadIdx.x & 31) == 0) red[threadIdx.x >> 5] = sum;
    __syncthreads();
    if (threadIdx.x == 0) g_v[k] = red[0] + red[1] + red[2] + red[3];
}

__global__ void __launch_bounds__(128) s2_k(const float* __restrict__ x) {
    int row = blockIdx.x;
    const float* xr = x + (size_t)row * DD;
    float sum = 0.f;
    for (int t = threadIdx.x; t < DD; t += 128) sum += xr[t] * g_v[t];
#pragma unroll
    for (int o = 16; o; o >>= 1) sum += __shfl_xor_sync(0xffffffffu, sum, o);
    __shared__ float red[4];
    if ((threadIdx.x & 31) == 0) red[threadIdx.x >> 5] = sum;
    __syncthreads();
    if (threadIdx.x == 0) g_s[row] = red[0] + red[1] + red[2] + red[3];
}

__global__ void yt_split_k() {
    __shared__ float t[32][33];
    int b = blockIdx.z;
    int i0 = blockIdx.x * 32, n0 = blockIdx.y * 32;
    const float* Y = g_y + (size_t)b * NN * DD;
    for (int r = threadIdx.y; r < 32; r += 8)
        t[r][threadIdx.x] = Y[(size_t)(i0 + r) * DD + n0 + threadIdx.x];
    __syncthreads();
    for (int r = threadIdx.y; r < 32; r += 8) {
        float v = t[threadIdx.x][r];                       // = Y[i0+tx][n0+r]
        size_t o = ((size_t)b * DD + n0 + r) * NN + i0 + threadIdx.x;
        __nv_bfloat16 h = __float2bfloat16(v);
        g_yth[o] = h;
        g_ytl[o] = __float2bfloat16(v - __bfloat162float(h));
    }
}

__global__ void __launch_bounds__(256) row_kernel(const float* __restrict__ A_shape) {
    const int row = blockIdx.x;             // b*NN + i
    const int b   = row >> 12;
    const float* arow = A_shape + (size_t)row * NN;
    const float* srow = g_s + (size_t)b * NN;
    const float  si   = g_s[row];

    __shared__ float Erow[NN];
    float deg = 0.f, R = 0.f;

    for (int j = threadIdx.x; j < NN; j += 256) {
        float aj = arow[j];
        float u  = (si + srow[j]) * 0.125f;
        float eu = __expf(-2.f * fabsf(u));
        float tt = (1.f - eu) / (1.f + eu);
        tt = copysignf(tt, u);
        float Av = 8.f * tt;
        Av = (Av >= 0.f) ? Av : 0.1f * Av;
        float e = __expf(Av) * aj;
        deg += aj; R += e;
        Erow[j] = e;
    }
#pragma unroll
    for (int o = 16; o; o >>= 1) {
        deg += __shfl_xor_sync(0xffffffffu, deg, o);
        R   += __shfl_xor_sync(0xffffffffu, R, o);
    }
    __shared__ float wdeg[8], wR[8], s_scale;
    const int warp = threadIdx.x >> 5;
    if ((threadIdx.x & 31) == 0) { wdeg[warp] = deg; wR[warp] = R; }
    __syncthreads();
    if (threadIdx.x == 0) {
        float D = 0.f, Rt = 0.f;
#pragma unroll
        for (int w2 = 0; w2 < 8; w2++) { D += wdeg[w2]; Rt += wR[w2]; }
        s_scale = D / Rt;
    }
    __syncthreads();
    const float sc = s_scale;

    __nv_bfloat16* eh = g_Eh + (size_t)row * NN;
    __nv_bfloat16* el = g_El + (size_t)row * NN;
    for (int j = threadIdx.x; j < NN; j += 256) {
        float e = Erow[j] * sc;
        __nv_bfloat16 h = __float2bfloat16(e);
        eh[j] = h;
        el[j] = __float2bfloat16(e - __bfloat162float(h));
    }
}

// ---------------- launch ----------------
extern "C" void kernel_launch(void* const* d_in, const int* in_sizes, int n_in,
                              void* d_out, int out_size)
{
    const float* x       = (const float*)d_in[0];
    const float* A_shape = (const float*)d_in[1];
    const float* w       = (const float*)d_in[2];
    const float* a       = (const float*)d_in[3];
    float* out = (float*)d_out;

    __nv_bfloat16 *pxh, *pxl, *pwth, *pwtl, *pyth, *pytl, *pEh, *pEl;
    float *py;
    cudaGetSymbolAddress((void**)&pxh,  g_xh);
    cudaGetSymbolAddress((void**)&pxl,  g_xl);
    cudaGetSymbolAddress((void**)&pwth, g_wth);
    cudaGetSymbolAddress((void**)&pwtl, g_wtl);
    cudaGetSymbolAddress((void**)&py,   g_y);
    cudaGetSymbolAddress((void**)&pyth, g_yth);
    cudaGetSymbolAddress((void**)&pytl, g_ytl);
    cudaGetSymbolAddress((void**)&pEh,  g_Eh);
    cudaGetSymbolAddress((void**)&pEl,  g_El);

    cudaFuncSetAttribute(gemm_mma, cudaFuncAttributeMaxDynamicSharedMemorySize, GEMM_SMEM);

    const int NX = BB * NN * DD;
    split_x_k<<<(NX + 255) / 256, 256>>>(x, NX);
    wt_split_k<<<(DD * DD) / 256, 256>>>(w);
    v_k<<<DD, 128>>>(w, a);
    s2_k<<<BB * NN, 128>>>(x);

    // y = x @ w   (M=16384, N=512, K=512)
    gemm_mma<<<dim3(DD / 128, (BB * NN) / 128, 1), 256, GEMM_SMEM>>>(
        pxh, pxl, pwth, pwtl, py, DD, DD, DD, DD, 0, 0, 0);

    yt_split_k<<<dim3(NN / 32, DD / 32, BB), dim3(32, 8)>>>();
    row_kernel<<<BB * NN, 256>>>(A_shape);

    // out[b] = E[b] @ Y^T[b]   (M=4096, N=512, K=4096, 4 batches)
    gemm_mma<<<dim3(DD / 128, NN / 128, BB), 256, GEMM_SMEM>>>(
        pEh, pEl, pyth, pytl, out,
        NN, NN, NN, DD,
        (long long)NN * NN, (long long)DD * NN, (long long)NN * DD);
}

// round 5
// speedup vs baseline: 2.8341x; 1.3186x over previous
#include <cuda_runtime.h>
#include <cuda_fp16.h>
#include <cstdint>
#include <math.h>

#define BB 4
#define NN 4096
#define DD 512

// ---------------- device scratch (allocation-free rule) ----------------
__device__ __half g_Eh[(size_t)BB * NN * NN];   // 134 MB, fp16 (single operand)
__device__ __half g_xh[(size_t)BB * NN * DD];
__device__ __half g_xl[(size_t)BB * NN * DD];
__device__ __half g_wth[DD * DD];
__device__ __half g_wtl[DD * DD];
__device__ float  g_y [(size_t)BB * NN * DD];   // fp32 y = x@w
__device__ __half g_yth[(size_t)BB * DD * NN];  // y^T split (B-operand layout)
__device__ __half g_ytl[(size_t)BB * DD * NN];
__device__ float  g_s [BB * NN];
__device__ float  g_v [DD];                     // v = w @ a

// ---------------- PTX helpers ----------------
__device__ __forceinline__ uint32_t smem_u32(const void* p) {
    uint32_t a;
    asm("{ .reg .u64 t; cvta.to.shared.u64 t, %1; cvt.u32.u64 %0, t; }" : "=r"(a) : "l"(p));
    return a;
}
__device__ __forceinline__ void cp16(uint32_t smem_addr, const void* gptr) {
    asm volatile("cp.async.cg.shared.global [%0], [%1], 16;" :: "r"(smem_addr), "l"(gptr));
}
#define CP_COMMIT() asm volatile("cp.async.commit_group;" ::: "memory")
template <int N> __device__ __forceinline__ void cp_wait() {
    asm volatile("cp.async.wait_group %0;" :: "n"(N) : "memory");
}
__device__ __forceinline__ void ldsm4(uint32_t& r0, uint32_t& r1, uint32_t& r2, uint32_t& r3,
                                      uint32_t addr) {
    asm volatile("ldmatrix.sync.aligned.m8n8.x4.shared.b16 {%0,%1,%2,%3}, [%4];"
                 : "=r"(r0), "=r"(r1), "=r"(r2), "=r"(r3) : "r"(addr));
}
__device__ __forceinline__ void mma16816(float* c, const uint32_t* a, const uint32_t* b) {
    asm volatile(
        "mma.sync.aligned.m16n8k16.row.col.f32.f16.f16.f32 "
        "{%0,%1,%2,%3}, {%4,%5,%6,%7}, {%8,%9}, {%0,%1,%2,%3};"
        : "+f"(c[0]), "+f"(c[1]), "+f"(c[2]), "+f"(c[3])
        : "r"(a[0]), "r"(a[1]), "r"(a[2]), "r"(a[3]), "r"(b[0]), "r"(b[1]));
}

// ---------------- fp16 mma.sync GEMM ----------------
// SPLIT_A = true : C = (Ah+Al) @ (Bh+Bl)^T  via AhBh + AhBl + AlBh (3 MMAs, ~exact)
// SPLIT_A = false: C =  Ah     @ (Bh+Bl)^T  via AhBh + AhBl        (2 MMAs)
// CTA tile 128x128, BK=32, cp.async pipeline, 8 warps (warp tile 32x64).
// smem rows padded to 80B -> conflict-free ldmatrix without swizzle.
#define ROWB 80
#define ABYTES (128 * ROWB)            // 10240 per matrix tile

template <bool SPLIT_A>
__global__ void __launch_bounds__(256) gemm_mma(
    const __half* __restrict__ Ah_, const __half* __restrict__ Al_,
    const __half* __restrict__ Bh_, const __half* __restrict__ Bl_,
    float* __restrict__ C_,
    int K, int lda, int ldb, int ldc,
    long long sAz, long long sBz, long long sCz)
{
    constexpr int NTILES = SPLIT_A ? 4 : 3;
    constexpr int STAGE_BYTES = NTILES * ABYTES;
    constexpr int STAGES = SPLIT_A ? 3 : 4;
    constexpr uint32_t STG_AH = 0;
    constexpr uint32_t STG_AL = SPLIT_A ? ABYTES : 0;          // unused if !SPLIT_A
    constexpr uint32_t STG_BH = SPLIT_A ? 2 * ABYTES : ABYTES;
    constexpr uint32_t STG_BL = SPLIT_A ? 3 * ABYTES : 2 * ABYTES;

    extern __shared__ char smem[];
    const uint32_t sb = smem_u32(smem);
    const int tid  = threadIdx.x;
    const int wid  = tid >> 5;
    const int lane = tid & 31;
    const int bcol = blockIdx.x * 128;
    const int brow = blockIdx.y * 128;
    const __half* Ah = Ah_ + (size_t)blockIdx.z * sAz;
    const __half* Al = Al_ + (size_t)blockIdx.z * sAz;
    const __half* Bh = Bh_ + (size_t)blockIdx.z * sBz;
    const __half* Bl = Bl_ + (size_t)blockIdx.z * sBz;
    float* C = C_ + (size_t)blockIdx.z * sCz;

    const int warp_m = wid & 3;        // 4 warps down M
    const int warp_n = wid >> 2;       // 2 warps across N
    const int m_base = warp_m * 32;
    const int n_base = warp_n * 64;

    float acc[2][8][4];
#pragma unroll
    for (int t = 0; t < 2; t++)
#pragma unroll
        for (int n = 0; n < 8; n++)
#pragma unroll
            for (int j = 0; j < 4; j++) acc[t][n][j] = 0.f;

    const int NCH = K >> 5;            // K chunks of 32

    auto load_chunk = [&](int c, int s) {
        const int k0 = c << 5;
        const uint32_t base = sb + s * STAGE_BYTES;
#pragma unroll
        for (int i = 0; i < 2; i++) {
            int id = tid + (i << 8);              // 0..511
            int r  = id >> 2;                     // row 0..127
            int ch = id & 3;                      // 16B chunk 0..3
            uint32_t so = r * ROWB + ch * 16;
            size_t ga = (size_t)(brow + r) * lda + k0 + ch * 8;
            size_t gb = (size_t)(bcol + r) * ldb + k0 + ch * 8;
            cp16(base + STG_AH + so, Ah + ga);
            if constexpr (SPLIT_A) cp16(base + STG_AL + so, Al + ga);
            cp16(base + STG_BH + so, Bh + gb);
            cp16(base + STG_BL + so, Bl + gb);
        }
    };

    // ldmatrix lane-address offsets (within a stage, relative to matrix base)
    const uint32_t aoff = (uint32_t)(m_base + (lane & 15)) * ROWB + (lane >> 4) * 16;
    const uint32_t boff = (uint32_t)(n_base + (lane & 7) + ((lane >> 4) << 3)) * ROWB
                        + ((lane >> 3) & 1) * 16;

    auto compute = [&](int s) {
        const uint32_t base = sb + s * STAGE_BYTES;
#pragma unroll
        for (int kk = 0; kk < 2; kk++) {          // two k16 steps per chunk
            const uint32_t kb = kk * 32;          // 16 fp16 = 32 bytes
            uint32_t ah[2][4], al[2][4], bh[4][4], bl[4][4];
#pragma unroll
            for (int t = 0; t < 2; t++) {
                uint32_t a_ad = base + aoff + (uint32_t)t * (16 * ROWB) + kb;
                ldsm4(ah[t][0], ah[t][1], ah[t][2], ah[t][3], STG_AH + a_ad);
                if constexpr (SPLIT_A)
                    ldsm4(al[t][0], al[t][1], al[t][2], al[t][3], STG_AL + a_ad);
            }
#pragma unroll
            for (int p = 0; p < 4; p++) {         // each covers n-tiles 2p, 2p+1
                uint32_t b_ad = base + boff + (uint32_t)p * (16 * ROWB) + kb;
                ldsm4(bh[p][0], bh[p][1], bh[p][2], bh[p][3], STG_BH + b_ad);
                ldsm4(bl[p][0], bl[p][1], bl[p][2], bl[p][3], STG_BL + b_ad);
            }
#pragma unroll
            for (int t = 0; t < 2; t++)
#pragma unroll
                for (int n = 0; n < 8; n++) {
                    const int p = n >> 1;
                    const uint32_t* fh = &bh[p][(n & 1) * 2];
                    const uint32_t* fl = &bl[p][(n & 1) * 2];
                    mma16816(acc[t][n], ah[t], fh);
                    mma16816(acc[t][n], ah[t], fl);
                    if constexpr (SPLIT_A) mma16816(acc[t][n], al[t], fh);
                }
        }
    };

    // prologue: prefetch STAGES-1 chunks
#pragma unroll
    for (int p = 0; p < STAGES - 1; p++) {
        if (p < NCH) load_chunk(p, p);
        CP_COMMIT();
    }

    for (int c = 0; c < NCH; c++) {
        cp_wait<STAGES - 2>();         // stage c data resident (this thread)
        __syncthreads();               // all threads' data visible
        if (c + STAGES - 1 < NCH) load_chunk(c + STAGES - 1, (c + STAGES - 1) % STAGES);
        CP_COMMIT();                   // uniform group counting (may be empty)
        compute(c % STAGES);
    }

    // epilogue: write fp32 accumulators
#pragma unroll
    for (int t = 0; t < 2; t++) {
        const int m0 = brow + m_base + t * 16 + (lane >> 2);
#pragma unroll
        for (int n = 0; n < 8; n++) {
            const int cn = bcol + n_base + n * 8 + (lane & 3) * 2;
            float2 v0 = make_float2(acc[t][n][0], acc[t][n][1]);
            float2 v1 = make_float2(acc[t][n][2], acc[t][n][3]);
            *(float2*)(C + (size_t)m0 * ldc + cn)       = v0;
            *(float2*)(C + (size_t)(m0 + 8) * ldc + cn) = v1;
        }
    }
}

#define GEMM_SMEM 122880   // both instantiations: 3*4*10240 == 4*3*10240

// ---------------- small kernels ----------------
// fused: split x -> fp16 h/l AND s[row] = dot(x[row], v)
__global__ void __launch_bounds__(128) split_s_k(const float* __restrict__ x) {
    const int row = blockIdx.x;
    const float* xr = x + (size_t)row * DD;
    __half* xh = g_xh + (size_t)row * DD;
    __half* xl = g_xl + (size_t)row * DD;
    float sum = 0.f;
#pragma unroll
    for (int q = 0; q < 4; q++) {
        int t = threadIdx.x + q * 128;
        float v = xr[t];
        __half h = __float2half(v);
        xh[t] = h;
        xl[t] = __float2half(v - __half2float(h));
        sum += v * g_v[t];
    }
#pragma unroll
    for (int o = 16; o; o >>= 1) sum += __shfl_xor_sync(0xffffffffu, sum, o);
    __shared__ float red[4];
    if ((threadIdx.x & 31) == 0) red[threadIdx.x >> 5] = sum;
    __syncthreads();
    if (threadIdx.x == 0) g_s[row] = red[0] + red[1] + red[2] + red[3];
}

__global__ void __launch_bounds__(256) wt_split_k(const float* __restrict__ w) {
    int id = blockIdx.x * 256 + threadIdx.x;   // id = n*512 + k
    int n = id >> 9, k = id & 511;
    float v = w[k * DD + n];                   // wt[n][k] = w[k][n]
    __half h = __float2half(v);
    g_wth[id] = h;
    g_wtl[id] = __float2half(v - __half2float(h));
}

__global__ void __launch_bounds__(128) v_k(const float* __restrict__ w, const float* __restrict__ a) {
    int k = blockIdx.x;
    float sum = 0.f;
    for (int t = threadIdx.x; t < DD; t += 128) sum += w[k * DD + t] * a[t];
#pragma unroll
    for (int o = 16; o; o >>= 1) sum += __shfl_xor_sync(0xffffffffu, sum, o);
    __shared__ float red[4];
    if ((threadIdx.x & 31) == 0) red[threadIdx.x >> 5] = sum;
    __syncthreads();
    if (threadIdx.x == 0) g_v[k] = red[0] + red[1] + red[2] + red[3];
}

__global__ void yt_split_k() {
    __shared__ float t[32][33];
    int b = blockIdx.z;
    int i0 = blockIdx.x * 32, n0 = blockIdx.y * 32;
    const float* Y = g_y + (size_t)b * NN * DD;
    for (int r = threadIdx.y; r < 32; r += 8)
        t[r][threadIdx.x] = Y[(size_t)(i0 + r) * DD + n0 + threadIdx.x];
    __syncthreads();
    for (int r = threadIdx.y; r < 32; r += 8) {
        float v = t[threadIdx.x][r];                       // = Y[i0+tx][n0+r]
        size_t o = ((size_t)b * DD + n0 + r) * NN + i0 + threadIdx.x;
        __half h = __float2half(v);
        g_yth[o] = h;
        g_ytl[o] = __float2half(v - __half2float(h));
    }
}

__global__ void __launch_bounds__(256) row_kernel(const float* __restrict__ A_shape) {
    const int row = blockIdx.x;             // b*NN + i
    const int b   = row >> 12;
    const float* arow = A_shape + (size_t)row * NN;
    const float* srow = g_s + (size_t)b * NN;
    const float  si   = g_s[row];

    __shared__ float Erow[NN];
    float deg = 0.f, R = 0.f;

    for (int j = threadIdx.x; j < NN; j += 256) {
        float aj = arow[j];
        float u  = (si + srow[j]) * 0.125f;
        float eu = __expf(-2.f * fabsf(u));
        float tt = (1.f - eu) / (1.f + eu);
        tt = copysignf(tt, u);
        float Av = 8.f * tt;
        Av = (Av >= 0.f) ? Av : 0.1f * Av;
        float e = __expf(Av) * aj;
        deg += aj; R += e;
        Erow[j] = e;
    }
#pragma unroll
    for (int o = 16; o; o >>= 1) {
        deg += __shfl_xor_sync(0xffffffffu, deg, o);
        R   += __shfl_xor_sync(0xffffffffu, R, o);
    }
    __shared__ float wdeg[8], wR[8], s_scale;
    const int warp = threadIdx.x >> 5;
    if ((threadIdx.x & 31) == 0) { wdeg[warp] = deg; wR[warp] = R; }
    __syncthreads();
    if (threadIdx.x == 0) {
        float D = 0.f, Rt = 0.f;
#pragma unroll
        for (int w2 = 0; w2 < 8; w2++) { D += wdeg[w2]; Rt += wR[w2]; }
        s_scale = D / Rt;
    }
    __syncthreads();
    const float sc = s_scale;

    __half* eh = g_Eh + (size_t)row * NN;
    for (int j = threadIdx.x; j < NN; j += 256)
        eh[j] = __float2half(Erow[j] * sc);
}

// ---------------- launch ----------------
extern "C" void kernel_launch(void* const* d_in, const int* in_sizes, int n_in,
                              void* d_out, int out_size)
{
    const float* x       = (const float*)d_in[0];
    const float* A_shape = (const float*)d_in[1];
    const float* w       = (const float*)d_in[2];
    const float* a       = (const float*)d_in[3];
    float* out = (float*)d_out;

    __half *pxh, *pxl, *pwth, *pwtl, *pyth, *pytl, *pEh;
    float *py;
    cudaGetSymbolAddress((void**)&pxh,  g_xh);
    cudaGetSymbolAddress((void**)&pxl,  g_xl);
    cudaGetSymbolAddress((void**)&pwth, g_wth);
    cudaGetSymbolAddress((void**)&pwtl, g_wtl);
    cudaGetSymbolAddress((void**)&py,   g_y);
    cudaGetSymbolAddress((void**)&pyth, g_yth);
    cudaGetSymbolAddress((void**)&pytl, g_ytl);
    cudaGetSymbolAddress((void**)&pEh,  g_Eh);

    cudaFuncSetAttribute(gemm_mma<true>,  cudaFuncAttributeMaxDynamicSharedMemorySize, GEMM_SMEM);
    cudaFuncSetAttribute(gemm_mma<false>, cudaFuncAttributeMaxDynamicSharedMemorySize, GEMM_SMEM);

    wt_split_k<<<(DD * DD) / 256, 256>>>(w);
    v_k<<<DD, 128>>>(w, a);
    split_s_k<<<BB * NN, 128>>>(x);

    // y = x @ w   (M=16384, N=512, K=512) -- exact 3-MMA split
    gemm_mma<true><<<dim3(DD / 128, (BB * NN) / 128, 1), 256, GEMM_SMEM>>>(
        pxh, pxl, pwth, pwtl, py, DD, DD, DD, DD, 0, 0, 0);

    yt_split_k<<<dim3(NN / 32, DD / 32, BB), dim3(32, 8)>>>();
    row_kernel<<<BB * NN, 256>>>(A_shape);

    // out[b] = E[b] @ Y^T[b]  (M=4096, N=512, K=4096, 4 batches) -- 2-MMA
    gemm_mma<false><<<dim3(DD / 128, NN / 128, BB), 256, GEMM_SMEM>>>(
        pEh, pEh, pyth, pytl, out,
        NN, NN, NN, DD,
        (long long)NN * NN, (long long)DD * NN, (long long)NN * DD);
}

// round 6
// speedup vs baseline: 4.5100x; 1.5913x over previous
#include <cuda_runtime.h>
#include <cuda_fp16.h>
#include <cstdint>
#include <math.h>

#define BB 4
#define NN 4096
#define DD 512

// ---------------- device scratch (allocation-free rule) ----------------
__device__ __half g_Eh[(size_t)BB * NN * NN];   // 134 MB, fp16
__device__ __half g_xh[(size_t)BB * NN * DD];
__device__ __half g_wth[DD * DD];
__device__ __half g_wtl[DD * DD];
__device__ float  g_y [(size_t)BB * NN * DD];   // fp32 y = x@w
__device__ __half g_yth[(size_t)BB * DD * NN];  // y^T fp16 (B-operand layout)
__device__ float  g_s [BB * NN];
__device__ float  g_v [DD];                     // v = w @ a

// ---------------- PTX helpers ----------------
__device__ __forceinline__ uint32_t smem_u32(const void* p) {
    uint32_t a;
    asm("{ .reg .u64 t; cvta.to.shared.u64 t, %1; cvt.u32.u64 %0, t; }" : "=r"(a) : "l"(p));
    return a;
}
__device__ __forceinline__ void cp16(uint32_t smem_addr, const void* gptr) {
    asm volatile("cp.async.cg.shared.global [%0], [%1], 16;" :: "r"(smem_addr), "l"(gptr));
}
#define CP_COMMIT() asm volatile("cp.async.commit_group;" ::: "memory")
template <int N> __device__ __forceinline__ void cp_wait() {
    asm volatile("cp.async.wait_group %0;" :: "n"(N) : "memory");
}
__device__ __forceinline__ void ldsm4(uint32_t& r0, uint32_t& r1, uint32_t& r2, uint32_t& r3,
                                      uint32_t addr) {
    asm volatile("ldmatrix.sync.aligned.m8n8.x4.shared.b16 {%0,%1,%2,%3}, [%4];"
                 : "=r"(r0), "=r"(r1), "=r"(r2), "=r"(r3) : "r"(addr));
}
__device__ __forceinline__ void mma16816(float* c, const uint32_t* a, const uint32_t* b) {
    asm volatile(
        "mma.sync.aligned.m16n8k16.row.col.f32.f16.f16.f32 "
        "{%0,%1,%2,%3}, {%4,%5,%6,%7}, {%8,%9}, {%0,%1,%2,%3};"
        : "+f"(c[0]), "+f"(c[1]), "+f"(c[2]), "+f"(c[3])
        : "r"(a[0]), "r"(a[1]), "r"(a[2]), "r"(a[3]), "r"(b[0]), "r"(b[1]));
}

// ---------------- fp16 mma.sync GEMM ----------------
// SPLIT_B = true : C = Ah @ (Bh+Bl)^T   (2 MMAs/tile-pair)
// SPLIT_B = false: C = Ah @ Bh^T        (1 MMA/tile-pair)
// CTA tile 128x128, BK=32, cp.async multi-stage, 8 warps (warp tile 32x64).
// smem rows padded to 80B -> conflict-free ldmatrix without swizzle.
#define ROWB 80
#define ABYTES (128 * ROWB)            // 10240 per matrix tile

template <bool SPLIT_B>
__global__ void __launch_bounds__(256, SPLIT_B ? 1 : 2) gemm_mma(
    const __half* __restrict__ Ah_,
    const __half* __restrict__ Bh_, const __half* __restrict__ Bl_,
    float* __restrict__ C_,
    int K, int lda, int ldb, int ldc,
    long long sAz, long long sBz, long long sCz)
{
    constexpr int NTILES = SPLIT_B ? 3 : 2;
    constexpr int STAGE_BYTES = NTILES * ABYTES;
    constexpr int STAGES = SPLIT_B ? 4 : 5;
    constexpr uint32_t STG_AH = 0;
    constexpr uint32_t STG_BH = ABYTES;
    constexpr uint32_t STG_BL = 2 * ABYTES;    // unused if !SPLIT_B

    extern __shared__ char smem[];
    const uint32_t sb = smem_u32(smem);
    const int tid  = threadIdx.x;
    const int wid  = tid >> 5;
    const int lane = tid & 31;
    const int bcol = blockIdx.x * 128;
    const int brow = blockIdx.y * 128;
    const __half* Ah = Ah_ + (size_t)blockIdx.z * sAz;
    const __half* Bh = Bh_ + (size_t)blockIdx.z * sBz;
    const __half* Bl = Bl_ + (size_t)blockIdx.z * sBz;
    float* C = C_ + (size_t)blockIdx.z * sCz;

    const int warp_m = wid & 3;        // 4 warps down M
    const int warp_n = wid >> 2;       // 2 warps across N
    const int m_base = warp_m * 32;
    const int n_base = warp_n * 64;

    float acc[2][8][4];
#pragma unroll
    for (int t = 0; t < 2; t++)
#pragma unroll
        for (int n = 0; n < 8; n++)
#pragma unroll
            for (int j = 0; j < 4; j++) acc[t][n][j] = 0.f;

    const int NCH = K >> 5;            // K chunks of 32

    auto load_chunk = [&](int c, int s) {
        const int k0 = c << 5;
        const uint32_t base = sb + s * STAGE_BYTES;
#pragma unroll
        for (int i = 0; i < 2; i++) {
            int id = tid + (i << 8);              // 0..511
            int r  = id >> 2;                     // row 0..127
            int ch = id & 3;                      // 16B chunk 0..3
            uint32_t so = r * ROWB + ch * 16;
            size_t ga = (size_t)(brow + r) * lda + k0 + ch * 8;
            size_t gb = (size_t)(bcol + r) * ldb + k0 + ch * 8;
            cp16(base + STG_AH + so, Ah + ga);
            cp16(base + STG_BH + so, Bh + gb);
            if constexpr (SPLIT_B) cp16(base + STG_BL + so, Bl + gb);
        }
    };

    // ldmatrix lane-address offsets (within a stage, relative to matrix base)
    const uint32_t aoff = (uint32_t)(m_base + (lane & 15)) * ROWB + (lane >> 4) * 16;
    const uint32_t boff = (uint32_t)(n_base + (lane & 7) + ((lane >> 4) << 3)) * ROWB
                        + ((lane >> 3) & 1) * 16;

    auto compute = [&](int s) {
        const uint32_t base = sb + s * STAGE_BYTES;
#pragma unroll
        for (int kk = 0; kk < 2; kk++) {          // two k16 steps per chunk
            const uint32_t kb = kk * 32;          // 16 fp16 = 32 bytes
            uint32_t ah[2][4], bh[4][4], bl[4][4];
#pragma unroll
            for (int t = 0; t < 2; t++) {
                uint32_t a_ad = base + aoff + (uint32_t)t * (16 * ROWB) + kb;
                ldsm4(ah[t][0], ah[t][1], ah[t][2], ah[t][3], STG_AH + a_ad);
            }
#pragma unroll
            for (int p = 0; p < 4; p++) {         // each covers n-tiles 2p, 2p+1
                uint32_t b_ad = base + boff + (uint32_t)p * (16 * ROWB) + kb;
                ldsm4(bh[p][0], bh[p][1], bh[p][2], bh[p][3], STG_BH + b_ad);
                if constexpr (SPLIT_B)
                    ldsm4(bl[p][0], bl[p][1], bl[p][2], bl[p][3], STG_BL + b_ad);
            }
#pragma unroll
            for (int t = 0; t < 2; t++)
#pragma unroll
                for (int n = 0; n < 8; n++) {
                    const int p = n >> 1;
                    mma16816(acc[t][n], ah[t], &bh[p][(n & 1) * 2]);
                    if constexpr (SPLIT_B)
                        mma16816(acc[t][n], ah[t], &bl[p][(n & 1) * 2]);
                }
        }
    };

    // prologue: prefetch STAGES-1 chunks
#pragma unroll
    for (int p = 0; p < STAGES - 1; p++) {
        if (p < NCH) load_chunk(p, p);
        CP_COMMIT();
    }

    for (int c = 0; c < NCH; c++) {
        cp_wait<STAGES - 2>();         // stage c data resident (this thread)
        __syncthreads();               // all threads' data visible
        if (c + STAGES - 1 < NCH) load_chunk(c + STAGES - 1, (c + STAGES - 1) % STAGES);
        CP_COMMIT();                   // uniform group counting (may be empty)
        compute(c % STAGES);
    }

    // epilogue: write fp32 accumulators
#pragma unroll
    for (int t = 0; t < 2; t++) {
        const int m0 = brow + m_base + t * 16 + (lane >> 2);
#pragma unroll
        for (int n = 0; n < 8; n++) {
            const int cn = bcol + n_base + n * 8 + (lane & 3) * 2;
            float2 v0 = make_float2(acc[t][n][0], acc[t][n][1]);
            float2 v1 = make_float2(acc[t][n][2], acc[t][n][3]);
            *(float2*)(C + (size_t)m0 * ldc + cn)       = v0;
            *(float2*)(C + (size_t)(m0 + 8) * ldc + cn) = v1;
        }
    }
}

#define GEMM_SMEM_2 122880   // SPLIT_B: 4 stages x 3 tiles
#define GEMM_SMEM_1 102400   // plain:   5 stages x 2 tiles

// ---------------- small kernels ----------------
// fused: x -> fp16 high AND s[row] = dot(x[row], v) in fp32
__global__ void __launch_bounds__(128) split_s_k(const float* __restrict__ x) {
    const int row = blockIdx.x;
    const float* xr = x + (size_t)row * DD;
    __half* xh = g_xh + (size_t)row * DD;
    float sum = 0.f;
#pragma unroll
    for (int q = 0; q < 4; q++) {
        int t = threadIdx.x + q * 128;
        float v = xr[t];
        xh[t] = __float2half(v);
        sum += v * g_v[t];
    }
#pragma unroll
    for (int o = 16; o; o >>= 1) sum += __shfl_xor_sync(0xffffffffu, sum, o);
    __shared__ float red[4];
    if ((threadIdx.x & 31) == 0) red[threadIdx.x >> 5] = sum;
    __syncthreads();
    if (threadIdx.x == 0) g_s[row] = red[0] + red[1] + red[2] + red[3];
}

__global__ void __launch_bounds__(256) wt_split_k(const float* __restrict__ w) {
    int id = blockIdx.x * 256 + threadIdx.x;   // id = n*512 + k
    int n = id >> 9, k = id & 511;
    float v = w[k * DD + n];                   // wt[n][k] = w[k][n]
    __half h = __float2half(v);
    g_wth[id] = h;
    g_wtl[id] = __float2half(v - __half2float(h));
}

__global__ void __launch_bounds__(128) v_k(const float* __restrict__ w, const float* __restrict__ a) {
    int k = blockIdx.x;
    float sum = 0.f;
    for (int t = threadIdx.x; t < DD; t += 128) sum += w[k * DD + t] * a[t];
#pragma unroll
    for (int o = 16; o; o >>= 1) sum += __shfl_xor_sync(0xffffffffu, sum, o);
    __shared__ float red[4];
    if ((threadIdx.x & 31) == 0) red[threadIdx.x >> 5] = sum;
    __syncthreads();
    if (threadIdx.x == 0) g_v[k] = red[0] + red[1] + red[2] + red[3];
}

__global__ void yt_split_k() {
    __shared__ float t[32][33];
    int b = blockIdx.z;
    int i0 = blockIdx.x * 32, n0 = blockIdx.y * 32;
    const float* Y = g_y + (size_t)b * NN * DD;
    for (int r = threadIdx.y; r < 32; r += 8)
        t[r][threadIdx.x] = Y[(size_t)(i0 + r) * DD + n0 + threadIdx.x];
    __syncthreads();
    for (int r = threadIdx.y; r < 32; r += 8) {
        float v = t[threadIdx.x][r];                       // = Y[i0+tx][n0+r]
        size_t o = ((size_t)b * DD + n0 + r) * NN + i0 + threadIdx.x;
        g_yth[o] = __float2half(v);
    }
}

__global__ void __launch_bounds__(256) row_kernel(const float* __restrict__ A_shape) {
    const int row = blockIdx.x;             // b*NN + i
    const int b   = row >> 12;
    const float* arow = A_shape + (size_t)row * NN;
    const float* srow = g_s + (size_t)b * NN;
    const float  si   = g_s[row];

    __shared__ float Erow[NN];
    float deg = 0.f, R = 0.f;

    for (int j = threadIdx.x; j < NN; j += 256) {
        float aj = arow[j];
        float u  = (si + srow[j]) * 0.125f;
        float eu = __expf(-2.f * fabsf(u));
        float tt = (1.f - eu) / (1.f + eu);
        tt = copysignf(tt, u);
        float Av = 8.f * tt;
        Av = (Av >= 0.f) ? Av : 0.1f * Av;
        float e = __expf(Av) * aj;
        deg += aj; R += e;
        Erow[j] = e;
    }
#pragma unroll
    for (int o = 16; o; o >>= 1) {
        deg += __shfl_xor_sync(0xffffffffu, deg, o);
        R   += __shfl_xor_sync(0xffffffffu, R, o);
    }
    __shared__ float wdeg[8], wR[8], s_scale;
    const int warp = threadIdx.x >> 5;
    if ((threadIdx.x & 31) == 0) { wdeg[warp] = deg; wR[warp] = R; }
    __syncthreads();
    if (threadIdx.x == 0) {
        float D = 0.f, Rt = 0.f;
#pragma unroll
        for (int w2 = 0; w2 < 8; w2++) { D += wdeg[w2]; Rt += wR[w2]; }
        s_scale = D / Rt;
    }
    __syncthreads();
    const float sc = s_scale;

    __half* eh = g_Eh + (size_t)row * NN;
    for (int j = threadIdx.x; j < NN; j += 256)
        eh[j] = __float2half(Erow[j] * sc);
}

// ---------------- launch ----------------
extern "C" void kernel_launch(void* const* d_in, const int* in_sizes, int n_in,
                              void* d_out, int out_size)
{
    const float* x       = (const float*)d_in[0];
    const float* A_shape = (const float*)d_in[1];
    const float* w       = (const float*)d_in[2];
    const float* a       = (const float*)d_in[3];
    float* out = (float*)d_out;

    __half *pxh, *pwth, *pwtl, *pyth, *pEh;
    float *py;
    cudaGetSymbolAddress((void**)&pxh,  g_xh);
    cudaGetSymbolAddress((void**)&pwth, g_wth);
    cudaGetSymbolAddress((void**)&pwtl, g_wtl);
    cudaGetSymbolAddress((void**)&py,   g_y);
    cudaGetSymbolAddress((void**)&pyth, g_yth);
    cudaGetSymbolAddress((void**)&pEh,  g_Eh);

    cudaFuncSetAttribute(gemm_mma<true>,  cudaFuncAttributeMaxDynamicSharedMemorySize, GEMM_SMEM_2);
    cudaFuncSetAttribute(gemm_mma<false>, cudaFuncAttributeMaxDynamicSharedMemorySize, GEMM_SMEM_1);

    wt_split_k<<<(DD * DD) / 256, 256>>>(w);
    v_k<<<DD, 128>>>(w, a);
    split_s_k<<<BB * NN, 128>>>(x);

    // y = x @ w   (M=16384, N=512, K=512) -- 2-MMA (w split)
    gemm_mma<true><<<dim3(DD / 128, (BB * NN) / 128, 1), 256, GEMM_SMEM_2>>>(
        pxh, pwth, pwtl, py, DD, DD, DD, DD, 0, 0, 0);

    yt_split_k<<<dim3(NN / 32, DD / 32, BB), dim3(32, 8)>>>();
    row_kernel<<<BB * NN, 256>>>(A_shape);

    // out[b] = E[b] @ Y^T[b]  (M=4096, N=512, K=4096, 4 batches) -- 1-MMA
    gemm_mma<false><<<dim3(DD / 128, NN / 128, BB), 256, GEMM_SMEM_1>>>(
        pEh, pyth, pyth, out,
        NN, NN, NN, DD,
        (long long)NN * NN, (long long)DD * NN, (long long)NN * DD);
}

// round 8
// speedup vs baseline: 5.7053x; 1.2650x over previous
#include <cuda_runtime.h>
#include <cuda_fp16.h>
#include <cstdint>
#include <math.h>

#define BB 4
#define NN 4096
#define DD 512

// ---------------- device scratch (allocation-free rule) ----------------
__device__ __half g_Eh[(size_t)BB * NN * NN];   // 134 MB, fp16
__device__ __half g_xh[(size_t)BB * NN * DD];
__device__ __half g_wth[DD * DD];
__device__ __half g_wtl[DD * DD];
__device__ float  g_y [(size_t)BB * NN * DD];   // fp32 y = x@w
__device__ __half g_yth[(size_t)BB * DD * NN];  // y^T fp16 (B-operand layout)
__device__ float  g_s [BB * NN];
__device__ float  g_v [DD];                     // v = w @ a

// ---------------- PTX helpers ----------------
__device__ __forceinline__ uint32_t smem_u32(const void* p) {
    uint32_t a;
    asm("{ .reg .u64 t; cvta.to.shared.u64 t, %1; cvt.u32.u64 %0, t; }" : "=r"(a) : "l"(p));
    return a;
}
__device__ __forceinline__ void cp16(uint32_t smem_addr, const void* gptr) {
    asm volatile("cp.async.cg.shared.global [%0], [%1], 16;" :: "r"(smem_addr), "l"(gptr));
}
#define CP_COMMIT() asm volatile("cp.async.commit_group;" ::: "memory")
template <int N> __device__ __forceinline__ void cp_wait() {
    asm volatile("cp.async.wait_group %0;" :: "n"(N) : "memory");
}
__device__ __forceinline__ void ldsm4(uint32_t& r0, uint32_t& r1, uint32_t& r2, uint32_t& r3,
                                      uint32_t addr) {
    asm volatile("ldmatrix.sync.aligned.m8n8.x4.shared.b16 {%0,%1,%2,%3}, [%4];"
                 : "=r"(r0), "=r"(r1), "=r"(r2), "=r"(r3) : "r"(addr));
}
__device__ __forceinline__ void mma16816(float* c, const uint32_t* a, const uint32_t* b) {
    asm volatile(
        "mma.sync.aligned.m16n8k16.row.col.f32.f16.f16.f32 "
        "{%0,%1,%2,%3}, {%4,%5,%6,%7}, {%8,%9}, {%0,%1,%2,%3};"
        : "+f"(c[0]), "+f"(c[1]), "+f"(c[2]), "+f"(c[3])
        : "r"(a[0]), "r"(a[1]), "r"(a[2]), "r"(a[3]), "r"(b[0]), "r"(b[1]));
}

#define ROWB 80
#define ABYTES (128 * ROWB)            // 10240 per matrix tile

// ================= main GEMM: C = A @ B^T, fp16 1-MMA =================
// CTA 128x128, 128 threads (4 warps), warp tile 64x64, BK=32, 5 stages.
#define MSTAGES 5
#define MSTAGE_BYTES (2 * ABYTES)          // 20480
#define GEMM1_SMEM (MSTAGES * MSTAGE_BYTES)  // 102400

__global__ void __launch_bounds__(128, 2) gemm_main(
    const __half* __restrict__ A_, const __half* __restrict__ B_,
    float* __restrict__ C_,
    int K, int lda, int ldb, int ldc,
    long long sAz, long long sBz, long long sCz)
{
    extern __shared__ char smem[];
    const uint32_t sb = smem_u32(smem);
    const int tid  = threadIdx.x;
    const int wid  = tid >> 5;
    const int lane = tid & 31;
    const int bcol = blockIdx.x * 128;
    const int brow = blockIdx.y * 128;
    const __half* A = A_ + (size_t)blockIdx.z * sAz;
    const __half* B = B_ + (size_t)blockIdx.z * sBz;
    float* C = C_ + (size_t)blockIdx.z * sCz;

    const int m_base = (wid & 1) * 64;
    const int n_base = (wid >> 1) * 64;

    float acc[4][8][4];
#pragma unroll
    for (int t = 0; t < 4; t++)
#pragma unroll
        for (int n = 0; n < 8; n++)
#pragma unroll
            for (int j = 0; j < 4; j++) acc[t][n][j] = 0.f;

    const int NCH = K >> 5;

    auto load_chunk = [&](int c, int s) {
        const int k0 = c << 5;
        const uint32_t base = sb + s * MSTAGE_BYTES;
#pragma unroll
        for (int i = 0; i < 4; i++) {
            int id = tid + (i << 7);              // 0..511
            int r  = id >> 2;                     // row 0..127
            int ch = id & 3;                      // 16B chunk
            uint32_t so = r * ROWB + ch * 16;
            cp16(base + so,          A + (size_t)(brow + r) * lda + k0 + ch * 8);
            cp16(base + ABYTES + so, B + (size_t)(bcol + r) * ldb + k0 + ch * 8);
        }
    };

    const uint32_t aoff = (uint32_t)(m_base + (lane & 15)) * ROWB + (lane >> 4) * 16;
    const uint32_t boff = (uint32_t)(n_base + (lane & 7) + ((lane >> 4) << 3)) * ROWB
                        + ((lane >> 3) & 1) * 16;

    auto compute = [&](int s) {
        const uint32_t base = sb + s * MSTAGE_BYTES;
#pragma unroll
        for (int kk = 0; kk < 2; kk++) {
            const uint32_t kb = kk * 32;
            uint32_t af[4][4], bf[4][4];
#pragma unroll
            for (int t = 0; t < 4; t++)
                ldsm4(af[t][0], af[t][1], af[t][2], af[t][3],
                      base + aoff + (uint32_t)t * (16 * ROWB) + kb);
#pragma unroll
            for (int p = 0; p < 4; p++)
                ldsm4(bf[p][0], bf[p][1], bf[p][2], bf[p][3],
                      base + ABYTES + boff + (uint32_t)p * (16 * ROWB) + kb);
#pragma unroll
            for (int t = 0; t < 4; t++)
#pragma unroll
                for (int n = 0; n < 8; n++)
                    mma16816(acc[t][n], af[t], &bf[n >> 1][(n & 1) * 2]);
        }
    };

#pragma unroll
    for (int p = 0; p < MSTAGES - 1; p++) {
        if (p < NCH) load_chunk(p, p);
        CP_COMMIT();
    }
    for (int c = 0; c < NCH; c++) {
        cp_wait<MSTAGES - 2>();
        __syncthreads();
        if (c + MSTAGES - 1 < NCH) load_chunk(c + MSTAGES - 1, (c + MSTAGES - 1) % MSTAGES);
        CP_COMMIT();
        compute(c % MSTAGES);
    }

#pragma unroll
    for (int t = 0; t < 4; t++) {
        const int m0 = brow + m_base + t * 16 + (lane >> 2);
#pragma unroll
        for (int n = 0; n < 8; n++) {
            const int cn = bcol + n_base + n * 8 + (lane & 3) * 2;
            *(float2*)(C + (size_t)m0 * ldc + cn)       = make_float2(acc[t][n][0], acc[t][n][1]);
            *(float2*)(C + (size_t)(m0 + 8) * ldc + cn) = make_float2(acc[t][n][2], acc[t][n][3]);
        }
    }
}

// ================= y GEMM: C = Ah @ (Bh+Bl)^T, 2-MMA split-B =================
// CTA 128x128, 256 threads (8 warps), warp tile 32x64, BK=32, 4 stages.
#define YSTAGE_BYTES (3 * ABYTES)
#define YSTAGES 4
#define GEMM2_SMEM (YSTAGES * YSTAGE_BYTES)   // 122880

__global__ void __launch_bounds__(256) gemm_y(
    const __half* __restrict__ Ah, const __half* __restrict__ Bh,
    const __half* __restrict__ Bl, float* __restrict__ C,
    int K, int lda, int ldb, int ldc)
{
    constexpr uint32_t STG_BH = ABYTES, STG_BL = 2 * ABYTES;
    extern __shared__ char smem[];
    const uint32_t sb = smem_u32(smem);
    const int tid  = threadIdx.x;
    const int wid  = tid >> 5;
    const int lane = tid & 31;
    const int bcol = blockIdx.x * 128;
    const int brow = blockIdx.y * 128;

    const int m_base = (wid & 3) * 32;
    const int n_base = (wid >> 2) * 64;

    float acc[2][8][4];
#pragma unroll
    for (int t = 0; t < 2; t++)
#pragma unroll
        for (int n = 0; n < 8; n++)
#pragma unroll
            for (int j = 0; j < 4; j++) acc[t][n][j] = 0.f;

    const int NCH = K >> 5;

    auto load_chunk = [&](int c, int s) {
        const int k0 = c << 5;
        const uint32_t base = sb + s * YSTAGE_BYTES;
#pragma unroll
        for (int i = 0; i < 2; i++) {
            int id = tid + (i << 8);
            int r  = id >> 2;
            int ch = id & 3;
            uint32_t so = r * ROWB + ch * 16;
            size_t ga = (size_t)(brow + r) * lda + k0 + ch * 8;
            size_t gb = (size_t)(bcol + r) * ldb + k0 + ch * 8;
            cp16(base + so, Ah + ga);
            cp16(base + STG_BH + so, Bh + gb);
            cp16(base + STG_BL + so, Bl + gb);
        }
    };

    const uint32_t aoff = (uint32_t)(m_base + (lane & 15)) * ROWB + (lane >> 4) * 16;
    const uint32_t boff = (uint32_t)(n_base + (lane & 7) + ((lane >> 4) << 3)) * ROWB
                        + ((lane >> 3) & 1) * 16;

    auto compute = [&](int s) {
        const uint32_t base = sb + s * YSTAGE_BYTES;
#pragma unroll
        for (int kk = 0; kk < 2; kk++) {
            const uint32_t kb = kk * 32;
            uint32_t ah[2][4], bh[4][4], bl[4][4];
#pragma unroll
            for (int t = 0; t < 2; t++)
                ldsm4(ah[t][0], ah[t][1], ah[t][2], ah[t][3],
                      base + aoff + (uint32_t)t * (16 * ROWB) + kb);
#pragma unroll
            for (int p = 0; p < 4; p++) {
                uint32_t b_ad = base + boff + (uint32_t)p * (16 * ROWB) + kb;
                ldsm4(bh[p][0], bh[p][1], bh[p][2], bh[p][3], STG_BH + b_ad);
                ldsm4(bl[p][0], bl[p][1], bl[p][2], bl[p][3], STG_BL + b_ad);
            }
#pragma unroll
            for (int t = 0; t < 2; t++)
#pragma unroll
                for (int n = 0; n < 8; n++) {
                    const int p = n >> 1;
                    mma16816(acc[t][n], ah[t], &bh[p][(n & 1) * 2]);
                    mma16816(acc[t][n], ah[t], &bl[p][(n & 1) * 2]);
                }
        }
    };

#pragma unroll
    for (int p = 0; p < YSTAGES - 1; p++) {
        if (p < NCH) load_chunk(p, p);
        CP_COMMIT();
    }
    for (int c = 0; c < NCH; c++) {
        cp_wait<YSTAGES - 2>();
        __syncthreads();
        if (c + YSTAGES - 1 < NCH) load_chunk(c + YSTAGES - 1, (c + YSTAGES - 1) % YSTAGES);
        CP_COMMIT();
        compute(c % YSTAGES);
    }

#pragma unroll
    for (int t = 0; t < 2; t++) {
        const int m0 = brow + m_base + t * 16 + (lane >> 2);
#pragma unroll
        for (int n = 0; n < 8; n++) {
            const int cn = bcol + n_base + n * 8 + (lane & 3) * 2;
            *(float2*)(C + (size_t)m0 * ldc + cn)       = make_float2(acc[t][n][0], acc[t][n][1]);
            *(float2*)(C + (size_t)(m0 + 8) * ldc + cn) = make_float2(acc[t][n][2], acc[t][n][3]);
        }
    }
}

// ---------------- small kernels ----------------
__global__ void __launch_bounds__(128) split_s_k(const float* __restrict__ x) {
    const int row = blockIdx.x;
    float4 xv = ((const float4*)(x + (size_t)row * DD))[threadIdx.x];
    float4 vv = ((const float4*)g_v)[threadIdx.x];
    __half2 h01 = __floats2half2_rn(xv.x, xv.y);
    __half2 h23 = __floats2half2_rn(xv.z, xv.w);
    uint2 pk = make_uint2(*(uint32_t*)&h01, *(uint32_t*)&h23);
    *(uint2*)(g_xh + (size_t)row * DD + threadIdx.x * 4) = pk;
    float sum = xv.x * vv.x + xv.y * vv.y + xv.z * vv.z + xv.w * vv.w;
#pragma unroll
    for (int o = 16; o; o >>= 1) sum += __shfl_xor_sync(0xffffffffu, sum, o);
    __shared__ float red[4];
    if ((threadIdx.x & 31) == 0) red[threadIdx.x >> 5] = sum;
    __syncthreads();
    if (threadIdx.x == 0) g_s[row] = red[0] + red[1] + red[2] + red[3];
}

__global__ void __launch_bounds__(256) wt_split_k(const float* __restrict__ w) {
    int id = blockIdx.x * 256 + threadIdx.x;   // id = n*512 + k
    int n = id >> 9, k = id & 511;
    float v = w[k * DD + n];
    __half h = __float2half(v);
    g_wth[id] = h;
    g_wtl[id] = __float2half(v - __half2float(h));
}

__global__ void __launch_bounds__(128) v_k(const float* __restrict__ w, const float* __restrict__ a) {
    int k = blockIdx.x;
    float sum = 0.f;
    for (int t = threadIdx.x; t < DD; t += 128) sum += w[k * DD + t] * a[t];
#pragma unroll
    for (int o = 16; o; o >>= 1) sum += __shfl_xor_sync(0xffffffffu, sum, o);
    __shared__ float red[4];
    if ((threadIdx.x & 31) == 0) red[threadIdx.x >> 5] = sum;
    __syncthreads();
    if (threadIdx.x == 0) g_v[k] = red[0] + red[1] + red[2] + red[3];
}

// transpose y -> y^T fp16, 64(i) x 32(n) tiles, half2 stores
__global__ void __launch_bounds__(256) yt_split_k() {
    __shared__ float tb[32][65];
    const int tx = threadIdx.x & 31, ty = threadIdx.x >> 5;
    const int b = blockIdx.z;
    const int i0 = blockIdx.x * 64, n0 = blockIdx.y * 32;
    const float* Y = g_y + (size_t)b * NN * DD;
#pragma unroll
    for (int rr = ty; rr < 64; rr += 8)
        tb[tx][rr] = Y[(size_t)(i0 + rr) * DD + n0 + tx];
    __syncthreads();
#pragma unroll
    for (int nn = ty; nn < 32; nn += 8) {
        __half2 h = __floats2half2_rn(tb[nn][tx * 2], tb[nn][tx * 2 + 1]);
        *(__half2*)(g_yth + ((size_t)b * DD + n0 + nn) * NN + i0 + tx * 2) = h;
    }
}

__global__ void __launch_bounds__(256) row_kernel(const float* __restrict__ A_shape) {
    const int row = blockIdx.x;             // b*NN + i
    const int b   = row >> 12;
    const float4* arow4 = (const float4*)(A_shape + (size_t)row * NN);
    const float4* srow4 = (const float4*)(g_s + (size_t)b * NN);
    const float  si   = g_s[row];

    __shared__ float Erow[NN];
    float deg = 0.f, R = 0.f;

#pragma unroll
    for (int q = 0; q < 4; q++) {
        int j4 = threadIdx.x + q * 256;
        float4 av = arow4[j4];
        float4 sv = srow4[j4];
        float e[4];
        float aa[4] = {av.x, av.y, av.z, av.w};
        float ss[4] = {sv.x, sv.y, sv.z, sv.w};
#pragma unroll
        for (int e2 = 0; e2 < 4; e2++) {
            float u  = (si + ss[e2]) * 0.125f;
            float eu = __expf(-2.f * fabsf(u));
            float tt = __fdividef(1.f - eu, 1.f + eu);
            tt = copysignf(tt, u);
            float Av = 8.f * tt;
            Av = (Av >= 0.f) ? Av : 0.1f * Av;
            e[e2] = __expf(Av) * aa[e2];
            deg += aa[e2]; R += e[e2];
        }
        ((float4*)Erow)[j4] = make_float4(e[0], e[1], e[2], e[3]);
    }
#pragma unroll
    for (int o = 16; o; o >>= 1) {
        deg += __shfl_xor_sync(0xffffffffu, deg, o);
        R   += __shfl_xor_sync(0xffffffffu, R, o);
    }
    __shared__ float wdeg[8], wR[8], s_scale;
    const int warp = threadIdx.x >> 5;
    if ((threadIdx.x & 31) == 0) { wdeg[warp] = deg; wR[warp] = R; }
    __syncthreads();
    if (threadIdx.x == 0) {
        float D = 0.f, Rt = 0.f;
#pragma unroll
        for (int w2 = 0; w2 < 8; w2++) { D += wdeg[w2]; Rt += wR[w2]; }
        s_scale = D / Rt;
    }
    __syncthreads();
    const float sc = s_scale;

    __half* eh = g_Eh + (size_t)row * NN;
#pragma unroll
    for (int q = 0; q < 4; q++) {
        int j4 = threadIdx.x + q * 256;
        float4 e4 = ((float4*)Erow)[j4];
        __half2 h01 = __floats2half2_rn(e4.x * sc, e4.y * sc);
        __half2 h23 = __floats2half2_rn(e4.z * sc, e4.w * sc);
        *(uint2*)(eh + j4 * 4) = make_uint2(*(uint32_t*)&h01, *(uint32_t*)&h23);
    }
}

// ---------------- launch ----------------
extern "C" void kernel_launch(void* const* d_in, const int* in_sizes, int n_in,
                              void* d_out, int out_size)
{
    const float* x       = (const float*)d_in[0];
    const float* A_shape = (const float*)d_in[1];
    const float* w       = (const float*)d_in[2];
    const float* a       = (const float*)d_in[3];
    float* out = (float*)d_out;

    __half *pxh, *pwth, *pwtl, *pyth, *pEh;
    float *py;
    cudaGetSymbolAddress((void**)&pxh,  g_xh);
    cudaGetSymbolAddress((void**)&pwth, g_wth);
    cudaGetSymbolAddress((void**)&pwtl, g_wtl);
    cudaGetSymbolAddress((void**)&py,   g_y);
    cudaGetSymbolAddress((void**)&pyth, g_yth);
    cudaGetSymbolAddress((void**)&pEh,  g_Eh);

    cudaFuncSetAttribute(gemm_y,    cudaFuncAttributeMaxDynamicSharedMemorySize, GEMM2_SMEM);
    cudaFuncSetAttribute(gemm_main, cudaFuncAttributeMaxDynamicSharedMemorySize, GEMM1_SMEM);

    wt_split_k<<<(DD * DD) / 256, 256>>>(w);
    v_k<<<DD, 128>>>(w, a);
    split_s_k<<<BB * NN, 128>>>(x);

    // y = x @ w   (M=16384, N=512, K=512) -- 2-MMA (w split)
    gemm_y<<<dim3(DD / 128, (BB * NN) / 128), 256, GEMM2_SMEM>>>(
        pxh, pwth, pwtl, py, DD, DD, DD, DD);

    yt_split_k<<<dim3(NN / 64, DD / 32, BB), 256>>>();
    row_kernel<<<BB * NN, 256>>>(A_shape);

    // out[b] = E[b] @ Y^T[b]  (M=4096, N=512, K=4096, 4 batches) -- 1-MMA
    gemm_main<<<dim3(DD / 128, NN / 128, BB), 128, GEMM1_SMEM>>>(
        pEh, pyth, out,
        NN, NN, NN, DD,
        (long long)NN * NN, (long long)DD * NN, (long long)NN * DD);
}